// round 12
// baseline (speedup 1.0000x reference)
#include <cuda_runtime.h>
#include <cstdint>

#define BB 32
#define CC 256
#define HWL 3136                // 56*56
#define HID 32
#define NPLANE (BB*CC)          // 8192
#define PLANE_BYTES (HWL * 4)   // 12544
#define NCTA 512
#define STAGES 16               // planes per CTA

__device__ float g_pooled[NPLANE];
__device__ unsigned g_cnt[STAGES];

__device__ __forceinline__ uint32_t smem_u32(const void* p) {
    return (uint32_t)__cvta_generic_to_shared(p);
}
__device__ __forceinline__ void tma_store_1d(void* dst, uint32_t src, uint32_t bytes) {
    asm volatile("cp.async.bulk.global.shared::cta.bulk_group [%0], [%1], %2;"
                 :: "l"(dst), "r"(src), "r"(bytes) : "memory");
}

__global__ __launch_bounds__(256, 4) void stream_kernel(
        const float* __restrict__ x,
        const float* __restrict__ fc1_w,
        const float* __restrict__ fc1_b,
        const float* __restrict__ fc2_w,
        const float* __restrict__ fc2_b,
        float* __restrict__ out) {
    __shared__ alignas(16) float buf[3][HWL];   // 37632 B ring
    __shared__ float ws[8];
    __shared__ float ps[CC];
    __shared__ float hs[HID];

    const int tid = threadIdx.x;
    const int lane = tid & 31;
    const int warp = tid >> 5;
    const int j = blockIdx.x;
    const uint32_t buf0 = smem_u32(buf[0]);

#pragma unroll 1
    for (int s = 0; s <= STAGES; s++) {
        const int cur = s % 3;

        // ---------------- pool plane 512*s + j into buf[cur] ----------------
        if (s < STAGES) {
            // buf[cur] was TMA-stored at stage s-2; allow stage s-1's store to
            // still be in flight.
            if (tid == 0 && s >= 2) {
                asm volatile("cp.async.bulk.wait_group 1;" ::: "memory");
            }
            __syncthreads();    // buf[cur] free for everyone

            const int p = 512 * s + j;
            const float4* xp = reinterpret_cast<const float4*>(x + (size_t)p * HWL);
            float4* t4 = reinterpret_cast<float4*>(buf[cur]);

            float4 v0 = xp[tid];
            float4 v1 = xp[tid + 256];
            float4 v2 = xp[tid + 512];
            t4[tid]       = v0;
            t4[tid + 256] = v1;
            t4[tid + 512] = v2;
            float sum = (v0.x + v0.y) + (v0.z + v0.w)
                      + (v1.x + v1.y) + (v1.z + v1.w)
                      + (v2.x + v2.y) + (v2.z + v2.w);
            if (tid < 16) {
                float4 v3 = xp[768 + tid];
                t4[768 + tid] = v3;
                sum += (v3.x + v3.y) + (v3.z + v3.w);
            }
#pragma unroll
            for (int o = 16; o > 0; o >>= 1) sum += __shfl_xor_sync(0xffffffffu, sum, o);
            if (lane == 0) ws[warp] = sum;
            __syncthreads();
            if (tid < 8) {
                sum = ws[tid];
#pragma unroll
                for (int o = 4; o > 0; o >>= 1) sum += __shfl_xor_sync(0xffu, sum, o);
                if (tid == 0) {
                    g_pooled[p] = sum * (1.0f / HWL);
                    __threadfence();
                    atomicAdd(&g_cnt[s], 1u);
                }
            }
        }

        // ---------------- apply plane 512*(s-1) + j from buf[(s-1)%3] -------
        if (s >= 1) {
            const int q = 512 * (s - 1) + j;
            const int pv = (s - 1) % 3;
            const int b = q >> 8;          // batch of prev plane
            const int c = q & 255;         // channel of prev plane

            if (tid == 0) {
                volatile unsigned* cnt = (volatile unsigned*)&g_cnt[s - 1];
                while (*cnt < NCTA) { __nanosleep(64); }
                __threadfence();
            }
            __syncthreads();

            // h for batch b (CTA-wide, 32 hidden x 8 partials)
            ps[tid] = __ldcg(&g_pooled[b * CC + tid]);
            __syncthreads();
            {
                const int jj = tid >> 3;
                const int part = tid & 7;
                const float* wrow = fc1_w + jj * CC + part * 32;
                const float* pp = ps + part * 32;
                float acc = 0.f;
#pragma unroll
                for (int i2 = 0; i2 < 32; i2++) acc = fmaf(pp[i2], wrow[i2], acc);
#pragma unroll
                for (int o = 4; o > 0; o >>= 1)
                    acc += __shfl_down_sync(0xffffffffu, acc, o, 8);
                if (part == 0) hs[jj] = fmaxf(acc + fc1_b[jj], 0.f);
            }
            __syncthreads();

            // coefficients (redundant per thread, broadcast loads)
            const float* wa0 = fc2_w + (size_t)(2 * c) * HID;
            const float* wb0 = wa0 + HID;
            const float* wa1 = fc2_w + (size_t)(2 * CC + 2 * c) * HID;
            const float* wb1 = wa1 + HID;
            float da0 = fc2_b[2 * c];
            float db0 = fc2_b[2 * c + 1];
            float da1 = fc2_b[2 * CC + 2 * c];
            float db1 = fc2_b[2 * CC + 2 * c + 1];
#pragma unroll
            for (int qq = 0; qq < HID; qq++) {
                float hq = hs[qq];
                da0 = fmaf(wa0[qq], hq, da0);
                db0 = fmaf(wb0[qq], hq, db0);
                da1 = fmaf(wa1[qq], hq, da1);
                db1 = fmaf(wb1[qq], hq, db1);
            }
            const float a0 = 1.0f + tanhf(0.5f * da0);          // LAMBDA_ALPHA=1
            const float c0 = 1.0f + 0.5f * tanhf(0.5f * db0);   // LAMBDA_BETA=.5
            const float a1 = tanhf(0.5f * da1);
            const float c1 = 0.5f * tanhf(0.5f * db1);

            // transform the stashed plane in place (zero global re-read)
            float4* t4 = reinterpret_cast<float4*>(buf[pv]);
            float4 v0 = t4[tid];
            float4 v1 = t4[tid + 256];
            float4 v2 = t4[tid + 512];
            float4 r0, r1, r2;
            r0.x = fmaxf(fmaf(v0.x, a0, c0), fmaf(v0.x, a1, c1));
            r0.y = fmaxf(fmaf(v0.y, a0, c0), fmaf(v0.y, a1, c1));
            r0.z = fmaxf(fmaf(v0.z, a0, c0), fmaf(v0.z, a1, c1));
            r0.w = fmaxf(fmaf(v0.w, a0, c0), fmaf(v0.w, a1, c1));
            r1.x = fmaxf(fmaf(v1.x, a0, c0), fmaf(v1.x, a1, c1));
            r1.y = fmaxf(fmaf(v1.y, a0, c0), fmaf(v1.y, a1, c1));
            r1.z = fmaxf(fmaf(v1.z, a0, c0), fmaf(v1.z, a1, c1));
            r1.w = fmaxf(fmaf(v1.w, a0, c0), fmaf(v1.w, a1, c1));
            r2.x = fmaxf(fmaf(v2.x, a0, c0), fmaf(v2.x, a1, c1));
            r2.y = fmaxf(fmaf(v2.y, a0, c0), fmaf(v2.y, a1, c1));
            r2.z = fmaxf(fmaf(v2.z, a0, c0), fmaf(v2.z, a1, c1));
            r2.w = fmaxf(fmaf(v2.w, a0, c0), fmaf(v2.w, a1, c1));
            t4[tid]       = r0;
            t4[tid + 256] = r1;
            t4[tid + 512] = r2;
            if (tid < 16) {
                float4 v3 = t4[768 + tid];
                float4 r3;
                r3.x = fmaxf(fmaf(v3.x, a0, c0), fmaf(v3.x, a1, c1));
                r3.y = fmaxf(fmaf(v3.y, a0, c0), fmaf(v3.y, a1, c1));
                r3.z = fmaxf(fmaf(v3.z, a0, c0), fmaf(v3.z, a1, c1));
                r3.w = fmaxf(fmaf(v3.w, a0, c0), fmaf(v3.w, a1, c1));
                t4[768 + tid] = r3;
            }
            __syncthreads();
            if (tid == 0) {
                asm volatile("fence.proxy.async.shared::cta;" ::: "memory");
                tma_store_1d(out + (size_t)q * HWL,
                             buf0 + (uint32_t)pv * PLANE_BYTES, PLANE_BYTES);
                asm volatile("cp.async.bulk.commit_group;" ::: "memory");
            }
        }
    }
    if (tid == 0) asm volatile("cp.async.bulk.wait_group 0;" ::: "memory");
}

extern "C" void kernel_launch(void* const* d_in, const int* in_sizes, int n_in,
                              void* d_out, int out_size) {
    const float* x      = (const float*)d_in[0];
    const float* fc1_w  = (const float*)d_in[1];
    const float* fc1_b  = (const float*)d_in[2];
    const float* fc2_w  = (const float*)d_in[3];
    const float* fc2_b  = (const float*)d_in[4];
    float* out = (float*)d_out;

    // zero the stage counters every call (graph-capturable memset node)
    void* cnt_ptr = nullptr;
    cudaGetSymbolAddress(&cnt_ptr, g_cnt);
    cudaMemsetAsync(cnt_ptr, 0, STAGES * sizeof(unsigned), 0);

    stream_kernel<<<NCTA, 256>>>(x, fc1_w, fc1_b, fc2_w, fc2_b, out);
}

// round 13
// speedup vs baseline: 2.7908x; 2.7908x over previous
#include <cuda_runtime.h>
#include <cstdint>

#define BB 32
#define CC 256
#define HWL 3136                // 56*56
#define HID 32
#define NPLANE (BB*CC)          // 8192
#define PLANE_BYTES (HWL * 4)   // 12544
#define NGROUP 4
#define GP (NPLANE / NGROUP)    // 2048 planes per group (= 8 batches)
#define GB (BB / NGROUP)        // 8 batches per group

__device__ float g_pooled[NPLANE];
__device__ float g_a0[NPLANE];
__device__ float g_c0[NPLANE];
__device__ float g_a1[NPLANE];
__device__ float g_c1[NPLANE];

__device__ __forceinline__ uint32_t smem_u32(const void* p) {
    return (uint32_t)__cvta_generic_to_shared(p);
}

// ---------------------------------------------------------------------------
// Kernel 1 (per group): mean over H*W. ONE WARP per plane, grid = 256 CTAs.
// Only ~14 warps/SM at this grid, so force deep MLP: all 24 main loads are
// issued before any reduction (plus 16-lane tail).
// ---------------------------------------------------------------------------
__global__ __launch_bounds__(256) void pool_kernel(const float* __restrict__ x,
                                                   int base_plane) {
    const int warp = (blockIdx.x << 3) | (threadIdx.x >> 5);
    const int plane = base_plane + warp;
    const int lane = threadIdx.x & 31;
    const float4* xp = reinterpret_cast<const float4*>(x + (size_t)plane * HWL);

    float4 r[24];
#pragma unroll
    for (int t = 0; t < 24; t++) r[t] = xp[lane + 32 * t];
    float4 vt;
    if (lane < 16) vt = xp[768 + lane];

    float s = 0.f;
#pragma unroll
    for (int t = 0; t < 24; t++) s += (r[t].x + r[t].y) + (r[t].z + r[t].w);
    if (lane < 16) s += (vt.x + vt.y) + (vt.z + vt.w);

#pragma unroll
    for (int o = 16; o > 0; o >>= 1) s += __shfl_xor_sync(0xffffffffu, s, o);
    if (lane == 0) g_pooled[plane] = s * (1.0f / HWL);
}

// ---------------------------------------------------------------------------
// Kernel 2 (per group): tiny MLP -> coefficient tables. Grid = 8 (one/batch).
// ---------------------------------------------------------------------------
__global__ __launch_bounds__(256) void coef_kernel(const float* __restrict__ fc1_w,
                                                   const float* __restrict__ fc1_b,
                                                   const float* __restrict__ fc2_w,
                                                   const float* __restrict__ fc2_b,
                                                   int base_batch) {
    const int b = base_batch + blockIdx.x;
    __shared__ float p_s[CC];
    __shared__ float h_s[HID];

    p_s[threadIdx.x] = g_pooled[b * CC + threadIdx.x];
    __syncthreads();

    {
        const int j = threadIdx.x >> 3;
        const int part = threadIdx.x & 7;
        const float* wrow = fc1_w + j * CC + part * 32;
        const float* pp = p_s + part * 32;
        float acc = 0.f;
#pragma unroll
        for (int i2 = 0; i2 < 32; i2++) acc = fmaf(pp[i2], wrow[i2], acc);
#pragma unroll
        for (int o = 4; o > 0; o >>= 1) acc += __shfl_down_sync(0xffffffffu, acc, o, 8);
        if (part == 0) h_s[j] = fmaxf(acc + fc1_b[j], 0.f);
    }
    __syncthreads();

    const int c = threadIdx.x;
    const float* wa0 = fc2_w + (size_t)(2 * c) * HID;
    const float* wb0 = wa0 + HID;
    const float* wa1 = fc2_w + (size_t)(2 * CC + 2 * c) * HID;
    const float* wb1 = wa1 + HID;
    float da0 = fc2_b[2 * c];
    float db0 = fc2_b[2 * c + 1];
    float da1 = fc2_b[2 * CC + 2 * c];
    float db1 = fc2_b[2 * CC + 2 * c + 1];
#pragma unroll
    for (int j = 0; j < HID; j++) {
        float hj = h_s[j];
        da0 = fmaf(wa0[j], hj, da0);
        db0 = fmaf(wb0[j], hj, db0);
        da1 = fmaf(wa1[j], hj, da1);
        db1 = fmaf(wb1[j], hj, db1);
    }
    const int plane = b * CC + c;
    g_a0[plane] = 1.0f + tanhf(0.5f * da0);          // LAMBDA_ALPHA = 1.0
    g_c0[plane] = 1.0f + 0.5f * tanhf(0.5f * db0);   // LAMBDA_BETA  = 0.5
    g_a1[plane] = tanhf(0.5f * da1);
    g_c1[plane] = 0.5f * tanhf(0.5f * db1);
}

// ---------------------------------------------------------------------------
// Kernel 3 (per group): hybrid apply. Grid = 2048, one CTA per plane,
// reversed within the group (freshest L2 lines first). LDG reads (group x is
// L2-hot from pool_g), evict-first TMA bulk store for writes.
// ---------------------------------------------------------------------------
__global__ __launch_bounds__(256, 8) void apply_kernel(const float* __restrict__ x,
                                                       float* __restrict__ out,
                                                       int base_plane) {
    __shared__ alignas(16) float tile[HWL];

    const int plane = base_plane + (GP - 1) - blockIdx.x;
    const int tid = threadIdx.x;

    const float a0 = g_a0[plane];
    const float c0 = g_c0[plane];
    const float a1 = g_a1[plane];
    const float c1 = g_c1[plane];

    const float4* xp = reinterpret_cast<const float4*>(x + (size_t)plane * HWL);
    float4* t4 = reinterpret_cast<float4*>(tile);

    float4 v0 = xp[tid];
    float4 v1 = xp[tid + 256];
    float4 v2 = xp[tid + 512];
    float4 r0, r1, r2;
    r0.x = fmaxf(fmaf(v0.x, a0, c0), fmaf(v0.x, a1, c1));
    r0.y = fmaxf(fmaf(v0.y, a0, c0), fmaf(v0.y, a1, c1));
    r0.z = fmaxf(fmaf(v0.z, a0, c0), fmaf(v0.z, a1, c1));
    r0.w = fmaxf(fmaf(v0.w, a0, c0), fmaf(v0.w, a1, c1));
    r1.x = fmaxf(fmaf(v1.x, a0, c0), fmaf(v1.x, a1, c1));
    r1.y = fmaxf(fmaf(v1.y, a0, c0), fmaf(v1.y, a1, c1));
    r1.z = fmaxf(fmaf(v1.z, a0, c0), fmaf(v1.z, a1, c1));
    r1.w = fmaxf(fmaf(v1.w, a0, c0), fmaf(v1.w, a1, c1));
    r2.x = fmaxf(fmaf(v2.x, a0, c0), fmaf(v2.x, a1, c1));
    r2.y = fmaxf(fmaf(v2.y, a0, c0), fmaf(v2.y, a1, c1));
    r2.z = fmaxf(fmaf(v2.z, a0, c0), fmaf(v2.z, a1, c1));
    r2.w = fmaxf(fmaf(v2.w, a0, c0), fmaf(v2.w, a1, c1));
    t4[tid]       = r0;
    t4[tid + 256] = r1;
    t4[tid + 512] = r2;
    if (tid < 16) {
        float4 v3 = xp[768 + tid];
        float4 r3;
        r3.x = fmaxf(fmaf(v3.x, a0, c0), fmaf(v3.x, a1, c1));
        r3.y = fmaxf(fmaf(v3.y, a0, c0), fmaf(v3.y, a1, c1));
        r3.z = fmaxf(fmaf(v3.z, a0, c0), fmaf(v3.z, a1, c1));
        r3.w = fmaxf(fmaf(v3.w, a0, c0), fmaf(v3.w, a1, c1));
        t4[768 + tid] = r3;
    }
    __syncthreads();

    if (tid == 0) {
        asm volatile("fence.proxy.async.shared::cta;" ::: "memory");
        asm volatile(
            "{\n\t"
            ".reg .b64 pol;\n\t"
            "createpolicy.fractional.L2::evict_first.b64 pol, 1.0;\n\t"
            "cp.async.bulk.global.shared::cta.bulk_group.L2::cache_hint "
            "[%0], [%1], %2, pol;\n\t"
            "}"
            :: "l"(out + (size_t)plane * HWL), "r"(smem_u32(tile)),
               "r"((uint32_t)PLANE_BYTES) : "memory");
        asm volatile("cp.async.bulk.commit_group;" ::: "memory");
        asm volatile("cp.async.bulk.wait_group 0;" ::: "memory");
    }
}

extern "C" void kernel_launch(void* const* d_in, const int* in_sizes, int n_in,
                              void* d_out, int out_size) {
    const float* x      = (const float*)d_in[0];
    const float* fc1_w  = (const float*)d_in[1];
    const float* fc1_b  = (const float*)d_in[2];
    const float* fc2_w  = (const float*)d_in[3];
    const float* fc2_b  = (const float*)d_in[4];
    float* out = (float*)d_out;

    for (int g = 0; g < NGROUP; g++) {
        const int base_plane = g * GP;
        const int base_batch = g * GB;
        pool_kernel<<<GP / 8, 256>>>(x, base_plane);
        coef_kernel<<<GB, 256>>>(fc1_w, fc1_b, fc2_w, fc2_b, base_batch);
        apply_kernel<<<GP, 256>>>(x, out, base_plane);
    }
}

// round 14
// speedup vs baseline: 5.7784x; 2.0705x over previous
#include <cuda_runtime.h>
#include <cstdint>

#define BB 32
#define CC 256
#define HWL 3136                // 56*56
#define HID 32
#define NPLANE (BB*CC)          // 8192
#define PLANE_BYTES (HWL * 4)   // 12544
#define APP_NP 4                // planes per apply CTA

__device__ float g_pooled[NPLANE];
__device__ float g_a0[NPLANE];
__device__ float g_c0[NPLANE];
__device__ float g_a1[NPLANE];
__device__ float g_c1[NPLANE];

__device__ __forceinline__ uint32_t smem_u32(const void* p) {
    return (uint32_t)__cvta_generic_to_shared(p);
}

// ---------------------------------------------------------------------------
// Kernel 1: mean over H*W per plane. ONE WARP per plane.
// 4 batches of 6 front-batched float4 loads -> MLP=6 per lane.
// ---------------------------------------------------------------------------
__global__ __launch_bounds__(256) void pool_kernel(const float* __restrict__ x) {
    const int warp = (blockIdx.x << 3) | (threadIdx.x >> 5);
    const int lane = threadIdx.x & 31;
    const float4* xp = reinterpret_cast<const float4*>(x + (size_t)warp * HWL);

    float s = 0.f;
    int i = lane;
#pragma unroll
    for (int g = 0; g < 4; g++) {
        float4 r[6];
#pragma unroll
        for (int t = 0; t < 6; t++) r[t] = xp[i + 32 * t];
        i += 192;
#pragma unroll
        for (int t = 0; t < 6; t++) s += (r[t].x + r[t].y) + (r[t].z + r[t].w);
    }
    if (lane < 16) {
        float4 v = xp[768 + lane];
        s += (v.x + v.y) + (v.z + v.w);
    }
#pragma unroll
    for (int o = 16; o > 0; o >>= 1) s += __shfl_xor_sync(0xffffffffu, s, o);
    if (lane == 0) g_pooled[warp] = s * (1.0f / HWL);
}

// ---------------------------------------------------------------------------
// Kernel 2: tiny MLP -> per-plane coefficient tables.
// ---------------------------------------------------------------------------
__global__ __launch_bounds__(256) void coef_kernel(const float* __restrict__ fc1_w,
                                                   const float* __restrict__ fc1_b,
                                                   const float* __restrict__ fc2_w,
                                                   const float* __restrict__ fc2_b) {
    const int b = blockIdx.x;
    __shared__ float p_s[CC];
    __shared__ float h_s[HID];

    p_s[threadIdx.x] = g_pooled[b * CC + threadIdx.x];
    __syncthreads();

    {
        const int j = threadIdx.x >> 3;
        const int part = threadIdx.x & 7;
        const float* wrow = fc1_w + j * CC + part * 32;
        const float* pp = p_s + part * 32;
        float acc = 0.f;
#pragma unroll
        for (int i2 = 0; i2 < 32; i2++) acc = fmaf(pp[i2], wrow[i2], acc);
#pragma unroll
        for (int o = 4; o > 0; o >>= 1) acc += __shfl_down_sync(0xffffffffu, acc, o, 8);
        if (part == 0) h_s[j] = fmaxf(acc + fc1_b[j], 0.f);
    }
    __syncthreads();

    const int c = threadIdx.x;
    const float* wa0 = fc2_w + (size_t)(2 * c) * HID;
    const float* wb0 = wa0 + HID;
    const float* wa1 = fc2_w + (size_t)(2 * CC + 2 * c) * HID;
    const float* wb1 = wa1 + HID;
    float da0 = fc2_b[2 * c];
    float db0 = fc2_b[2 * c + 1];
    float da1 = fc2_b[2 * CC + 2 * c];
    float db1 = fc2_b[2 * CC + 2 * c + 1];
#pragma unroll
    for (int j = 0; j < HID; j++) {
        float hj = h_s[j];
        da0 = fmaf(wa0[j], hj, da0);
        db0 = fmaf(wb0[j], hj, db0);
        da1 = fmaf(wa1[j], hj, da1);
        db1 = fmaf(wb1[j], hj, db1);
    }
    const int plane = b * CC + c;
    g_a0[plane] = 1.0f + tanhf(0.5f * da0);          // LAMBDA_ALPHA = 1.0
    g_c0[plane] = 1.0f + 0.5f * tanhf(0.5f * db0);   // LAMBDA_BETA  = 0.5
    g_a1[plane] = tanhf(0.5f * da1);
    g_c1[plane] = 0.5f * tanhf(0.5f * db1);
}

// ---------------------------------------------------------------------------
// Kernel 3: hybrid apply, 4 planes/CTA, double-buffered SMEM, store slack.
// Reads: plain LDG (reverse global order -> freshest L2 lines first).
// Writes: evict-first TMA bulk store; wait_group 1 keeps 2 stores in flight
// per CTA and hides each drain behind the next plane's load+compute.
// ---------------------------------------------------------------------------
__global__ __launch_bounds__(256, 8) void apply_kernel(const float* __restrict__ x,
                                                       float* __restrict__ out) {
    __shared__ alignas(16) float tile[2][HWL];   // 25088 B

    const int tid = threadIdx.x;
    // CTA i processes descending contiguous planes starting from the top.
    const int first = (NPLANE - 1) - blockIdx.x * APP_NP;

#pragma unroll
    for (int t = 0; t < APP_NP; t++) {
        const int plane = first - t;
        const int cur = t & 1;

        // Before overwriting tile[cur], drain the store issued on it at t-2.
        if (t >= 2 && tid == 0) {
            asm volatile("cp.async.bulk.wait_group 1;" ::: "memory");
        }
        if (t >= 1) __syncthreads();   // tile[cur] free for all threads

        const float a0 = g_a0[plane];
        const float c0 = g_c0[plane];
        const float a1 = g_a1[plane];
        const float c1 = g_c1[plane];

        const float4* xp = reinterpret_cast<const float4*>(x + (size_t)plane * HWL);
        float4* t4 = reinterpret_cast<float4*>(tile[cur]);

        float4 v0 = xp[tid];
        float4 v1 = xp[tid + 256];
        float4 v2 = xp[tid + 512];
        float4 r0, r1, r2;
        r0.x = fmaxf(fmaf(v0.x, a0, c0), fmaf(v0.x, a1, c1));
        r0.y = fmaxf(fmaf(v0.y, a0, c0), fmaf(v0.y, a1, c1));
        r0.z = fmaxf(fmaf(v0.z, a0, c0), fmaf(v0.z, a1, c1));
        r0.w = fmaxf(fmaf(v0.w, a0, c0), fmaf(v0.w, a1, c1));
        r1.x = fmaxf(fmaf(v1.x, a0, c0), fmaf(v1.x, a1, c1));
        r1.y = fmaxf(fmaf(v1.y, a0, c0), fmaf(v1.y, a1, c1));
        r1.z = fmaxf(fmaf(v1.z, a0, c0), fmaf(v1.z, a1, c1));
        r1.w = fmaxf(fmaf(v1.w, a0, c0), fmaf(v1.w, a1, c1));
        r2.x = fmaxf(fmaf(v2.x, a0, c0), fmaf(v2.x, a1, c1));
        r2.y = fmaxf(fmaf(v2.y, a0, c0), fmaf(v2.y, a1, c1));
        r2.z = fmaxf(fmaf(v2.z, a0, c0), fmaf(v2.z, a1, c1));
        r2.w = fmaxf(fmaf(v2.w, a0, c0), fmaf(v2.w, a1, c1));
        t4[tid]       = r0;
        t4[tid + 256] = r1;
        t4[tid + 512] = r2;
        if (tid < 16) {
            float4 v3 = xp[768 + tid];
            float4 r3;
            r3.x = fmaxf(fmaf(v3.x, a0, c0), fmaf(v3.x, a1, c1));
            r3.y = fmaxf(fmaf(v3.y, a0, c0), fmaf(v3.y, a1, c1));
            r3.z = fmaxf(fmaf(v3.z, a0, c0), fmaf(v3.z, a1, c1));
            r3.w = fmaxf(fmaf(v3.w, a0, c0), fmaf(v3.w, a1, c1));
            t4[768 + tid] = r3;
        }
        __syncthreads();

        if (tid == 0) {
            asm volatile("fence.proxy.async.shared::cta;" ::: "memory");
            asm volatile(
                "{\n\t"
                ".reg .b64 pol;\n\t"
                "createpolicy.fractional.L2::evict_first.b64 pol, 1.0;\n\t"
                "cp.async.bulk.global.shared::cta.bulk_group.L2::cache_hint "
                "[%0], [%1], %2, pol;\n\t"
                "}"
                :: "l"(out + (size_t)plane * HWL), "r"(smem_u32(tile[cur])),
                   "r"((uint32_t)PLANE_BYTES) : "memory");
            asm volatile("cp.async.bulk.commit_group;" ::: "memory");
        }
    }
    if (tid == 0) asm volatile("cp.async.bulk.wait_group 0;" ::: "memory");
}

extern "C" void kernel_launch(void* const* d_in, const int* in_sizes, int n_in,
                              void* d_out, int out_size) {
    const float* x      = (const float*)d_in[0];
    const float* fc1_w  = (const float*)d_in[1];
    const float* fc1_b  = (const float*)d_in[2];
    const float* fc2_w  = (const float*)d_in[3];
    const float* fc2_b  = (const float*)d_in[4];
    float* out = (float*)d_out;

    pool_kernel<<<NPLANE / 8, 256>>>(x);
    coef_kernel<<<BB, 256>>>(fc1_w, fc1_b, fc2_w, fc2_b);
    apply_kernel<<<NPLANE / APP_NP, 256>>>(x, out);
}

// round 15
// speedup vs baseline: 6.1288x; 1.0606x over previous
#include <cuda_runtime.h>
#include <cstdint>

#define BB 32
#define CC 256
#define HWL 3136                // 56*56
#define HID 32
#define NPLANE (BB*CC)          // 8192
#define PLANE_BYTES (HWL * 4)   // 12544

__device__ float g_pooled[NPLANE];
__device__ float g_a0[NPLANE];
__device__ float g_c0[NPLANE];
__device__ float g_a1[NPLANE];
__device__ float g_c1[NPLANE];

__device__ __forceinline__ uint32_t smem_u32(const void* p) {
    return (uint32_t)__cvta_generic_to_shared(p);
}

// ---------------------------------------------------------------------------
// Kernel 1: mean over H*W per plane. ONE WARP per plane. (best: 19.55us)
// ---------------------------------------------------------------------------
__global__ __launch_bounds__(256) void pool_kernel(const float* __restrict__ x) {
    const int warp = (blockIdx.x << 3) | (threadIdx.x >> 5);
    const int lane = threadIdx.x & 31;
    const float4* xp = reinterpret_cast<const float4*>(x + (size_t)warp * HWL);

    float s = 0.f;
    int i = lane;
#pragma unroll
    for (int g = 0; g < 4; g++) {
        float4 r[6];
#pragma unroll
        for (int t = 0; t < 6; t++) r[t] = xp[i + 32 * t];
        i += 192;
#pragma unroll
        for (int t = 0; t < 6; t++) s += (r[t].x + r[t].y) + (r[t].z + r[t].w);
    }
    if (lane < 16) {
        float4 v = xp[768 + lane];
        s += (v.x + v.y) + (v.z + v.w);
    }
#pragma unroll
    for (int o = 16; o > 0; o >>= 1) s += __shfl_xor_sync(0xffffffffu, s, o);
    if (lane == 0) g_pooled[warp] = s * (1.0f / HWL);
}

// ---------------------------------------------------------------------------
// Kernel 2: tiny MLP -> per-plane coefficient tables.
// ---------------------------------------------------------------------------
__global__ __launch_bounds__(256) void coef_kernel(const float* __restrict__ fc1_w,
                                                   const float* __restrict__ fc1_b,
                                                   const float* __restrict__ fc2_w,
                                                   const float* __restrict__ fc2_b) {
    const int b = blockIdx.x;
    __shared__ float p_s[CC];
    __shared__ float h_s[HID];

    p_s[threadIdx.x] = g_pooled[b * CC + threadIdx.x];
    __syncthreads();

    {
        const int j = threadIdx.x >> 3;
        const int part = threadIdx.x & 7;
        const float* wrow = fc1_w + j * CC + part * 32;
        const float* pp = p_s + part * 32;
        float acc = 0.f;
#pragma unroll
        for (int i2 = 0; i2 < 32; i2++) acc = fmaf(pp[i2], wrow[i2], acc);
#pragma unroll
        for (int o = 4; o > 0; o >>= 1) acc += __shfl_down_sync(0xffffffffu, acc, o, 8);
        if (part == 0) h_s[j] = fmaxf(acc + fc1_b[j], 0.f);
    }
    __syncthreads();

    const int c = threadIdx.x;
    const float* wa0 = fc2_w + (size_t)(2 * c) * HID;
    const float* wb0 = wa0 + HID;
    const float* wa1 = fc2_w + (size_t)(2 * CC + 2 * c) * HID;
    const float* wb1 = wa1 + HID;
    float da0 = fc2_b[2 * c];
    float db0 = fc2_b[2 * c + 1];
    float da1 = fc2_b[2 * CC + 2 * c];
    float db1 = fc2_b[2 * CC + 2 * c + 1];
#pragma unroll
    for (int j = 0; j < HID; j++) {
        float hj = h_s[j];
        da0 = fmaf(wa0[j], hj, da0);
        db0 = fmaf(wb0[j], hj, db0);
        da1 = fmaf(wa1[j], hj, da1);
        db1 = fmaf(wb1[j], hj, db1);
    }
    const int plane = b * CC + c;
    g_a0[plane] = 1.0f + tanhf(0.5f * da0);          // LAMBDA_ALPHA = 1.0
    g_c0[plane] = 1.0f + 0.5f * tanhf(0.5f * db0);   // LAMBDA_BETA  = 0.5
    g_a1[plane] = tanhf(0.5f * da1);
    g_c1[plane] = 0.5f * tanhf(0.5f * db1);
}

// ---------------------------------------------------------------------------
// Kernel 3: pure-TMA swarm apply. 64 threads/CTA, one plane/CTA, grid 8192.
// ~17 CTAs co-resident per SM (smem-bound, not thread-bound) -> ~17 concurrent
// TMA loads + stores per SM. Plane data never touches LDG/STG; only LDS/STS
// for the in-smem transform. Reverse order + evict-first store retained.
// ---------------------------------------------------------------------------
__global__ __launch_bounds__(64) void apply_tma64_kernel(const float* __restrict__ x,
                                                         float* __restrict__ out) {
    __shared__ alignas(16) float tile[HWL];
    __shared__ alignas(8) unsigned long long mbar;

    const int plane = (NPLANE - 1) - blockIdx.x;   // reverse traversal
    const int tid = threadIdx.x;
    const uint32_t mb = smem_u32(&mbar);
    const uint32_t ta = smem_u32(tile);

    if (tid == 0) {
        asm volatile("mbarrier.init.shared.b64 [%0], 1;" :: "r"(mb) : "memory");
        asm volatile("mbarrier.arrive.expect_tx.shared.b64 _, [%0], %1;"
                     :: "r"(mb), "r"((uint32_t)PLANE_BYTES) : "memory");
        asm volatile(
            "cp.async.bulk.shared::cluster.global.mbarrier::complete_tx::bytes "
            "[%0], [%1], %2, [%3];"
            :: "r"(ta), "l"(x + (size_t)plane * HWL),
               "r"((uint32_t)PLANE_BYTES), "r"(mb) : "memory");
    }
    __syncthreads();   // mbar init visible to all waiters

    // coefficient scalars (L2-resident tables), overlapped with the TMA load
    const float a0 = g_a0[plane];
    const float c0 = g_c0[plane];
    const float a1 = g_a1[plane];
    const float c1 = g_c1[plane];

    asm volatile(
        "{\n\t"
        ".reg .pred P;\n\t"
        "W_%=:\n\t"
        "mbarrier.try_wait.parity.shared.b64 P, [%0], 0;\n\t"
        "@!P bra W_%=;\n\t"
        "}"
        :: "r"(mb) : "memory");

    float4* t4 = reinterpret_cast<float4*>(tile);
    // 784 float4 over 64 threads: 12 each + 16-thread tail
#pragma unroll
    for (int k = 0; k < 12; k++) {
        float4 v = t4[tid + 64 * k];
        float4 r;
        r.x = fmaxf(fmaf(v.x, a0, c0), fmaf(v.x, a1, c1));
        r.y = fmaxf(fmaf(v.y, a0, c0), fmaf(v.y, a1, c1));
        r.z = fmaxf(fmaf(v.z, a0, c0), fmaf(v.z, a1, c1));
        r.w = fmaxf(fmaf(v.w, a0, c0), fmaf(v.w, a1, c1));
        t4[tid + 64 * k] = r;
    }
    if (tid < 16) {
        float4 v = t4[768 + tid];
        float4 r;
        r.x = fmaxf(fmaf(v.x, a0, c0), fmaf(v.x, a1, c1));
        r.y = fmaxf(fmaf(v.y, a0, c0), fmaf(v.y, a1, c1));
        r.z = fmaxf(fmaf(v.z, a0, c0), fmaf(v.z, a1, c1));
        r.w = fmaxf(fmaf(v.w, a0, c0), fmaf(v.w, a1, c1));
        t4[768 + tid] = r;
    }
    __syncthreads();

    if (tid == 0) {
        asm volatile("fence.proxy.async.shared::cta;" ::: "memory");
        asm volatile(
            "{\n\t"
            ".reg .b64 pol;\n\t"
            "createpolicy.fractional.L2::evict_first.b64 pol, 1.0;\n\t"
            "cp.async.bulk.global.shared::cta.bulk_group.L2::cache_hint "
            "[%0], [%1], %2, pol;\n\t"
            "}"
            :: "l"(out + (size_t)plane * HWL), "r"(ta),
               "r"((uint32_t)PLANE_BYTES) : "memory");
        asm volatile("cp.async.bulk.commit_group;" ::: "memory");
        asm volatile("cp.async.bulk.wait_group 0;" ::: "memory");
    }
}

extern "C" void kernel_launch(void* const* d_in, const int* in_sizes, int n_in,
                              void* d_out, int out_size) {
    const float* x      = (const float*)d_in[0];
    const float* fc1_w  = (const float*)d_in[1];
    const float* fc1_b  = (const float*)d_in[2];
    const float* fc2_w  = (const float*)d_in[3];
    const float* fc2_b  = (const float*)d_in[4];
    float* out = (float*)d_out;

    // maximize smem carveout so apply gets ~17 CTAs/SM
    static bool configured = false;
    if (!configured) {
        cudaFuncSetAttribute(apply_tma64_kernel,
                             cudaFuncAttributePreferredSharedMemoryCarveout, 100);
        configured = true;
    }

    pool_kernel<<<NPLANE / 8, 256>>>(x);
    coef_kernel<<<BB, 256>>>(fc1_w, fc1_b, fc2_w, fc2_b);
    apply_tma64_kernel<<<NPLANE, 64>>>(x, out);
}

// round 16
// speedup vs baseline: 6.3871x; 1.0421x over previous
#include <cuda_runtime.h>
#include <cstdint>

#define BB 32
#define CC 256
#define HWL 3136                // 56*56
#define HID 32
#define NPLANE (BB*CC)          // 8192
#define PLANE_BYTES (HWL * 4)   // 12544

__device__ float g_pooled[NPLANE];
__device__ float g_a0[NPLANE];
__device__ float g_c0[NPLANE];
__device__ float g_a1[NPLANE];
__device__ float g_c1[NPLANE];

__device__ __forceinline__ uint32_t smem_u32(const void* p) {
    return (uint32_t)__cvta_generic_to_shared(p);
}

// ---------------------------------------------------------------------------
// Kernel 1: TMA swarm pool. 64 threads/CTA, one plane/CTA, grid 8192.
// ~17 CTAs/SM -> ~213 KB of reads in flight per SM (vs 18 KB for LDG pool).
// Reduce happens from SMEM (LDS), far from binding.
// ---------------------------------------------------------------------------
__global__ __launch_bounds__(64) void pool_tma64_kernel(const float* __restrict__ x) {
    __shared__ alignas(16) float tile[HWL];
    __shared__ alignas(8) unsigned long long mbar;
    __shared__ float ws[2];

    const int plane = blockIdx.x;
    const int tid = threadIdx.x;
    const int lane = tid & 31;
    const int warp = tid >> 5;
    const uint32_t mb = smem_u32(&mbar);
    const uint32_t ta = smem_u32(tile);

    if (tid == 0) {
        asm volatile("mbarrier.init.shared.b64 [%0], 1;" :: "r"(mb) : "memory");
        asm volatile("mbarrier.arrive.expect_tx.shared.b64 _, [%0], %1;"
                     :: "r"(mb), "r"((uint32_t)PLANE_BYTES) : "memory");
        asm volatile(
            "cp.async.bulk.shared::cluster.global.mbarrier::complete_tx::bytes "
            "[%0], [%1], %2, [%3];"
            :: "r"(ta), "l"(x + (size_t)plane * HWL),
               "r"((uint32_t)PLANE_BYTES), "r"(mb) : "memory");
    }
    __syncthreads();

    asm volatile(
        "{\n\t"
        ".reg .pred P;\n\t"
        "W_%=:\n\t"
        "mbarrier.try_wait.parity.shared.b64 P, [%0], 0;\n\t"
        "@!P bra W_%=;\n\t"
        "}"
        :: "r"(mb) : "memory");

    const float4* t4 = reinterpret_cast<const float4*>(tile);
    float s = 0.f;
#pragma unroll
    for (int k = 0; k < 12; k++) {
        float4 v = t4[tid + 64 * k];
        s += (v.x + v.y) + (v.z + v.w);
    }
    if (tid < 16) {
        float4 v = t4[768 + tid];
        s += (v.x + v.y) + (v.z + v.w);
    }
#pragma unroll
    for (int o = 16; o > 0; o >>= 1) s += __shfl_xor_sync(0xffffffffu, s, o);
    if (lane == 0) ws[warp] = s;
    __syncthreads();
    if (tid == 0) g_pooled[plane] = (ws[0] + ws[1]) * (1.0f / HWL);
}

// ---------------------------------------------------------------------------
// Kernel 2: tiny MLP -> per-plane coefficient tables.
// ---------------------------------------------------------------------------
__global__ __launch_bounds__(256) void coef_kernel(const float* __restrict__ fc1_w,
                                                   const float* __restrict__ fc1_b,
                                                   const float* __restrict__ fc2_w,
                                                   const float* __restrict__ fc2_b) {
    const int b = blockIdx.x;
    __shared__ float p_s[CC];
    __shared__ float h_s[HID];

    p_s[threadIdx.x] = g_pooled[b * CC + threadIdx.x];
    __syncthreads();

    {
        const int j = threadIdx.x >> 3;
        const int part = threadIdx.x & 7;
        const float* wrow = fc1_w + j * CC + part * 32;
        const float* pp = p_s + part * 32;
        float acc = 0.f;
#pragma unroll
        for (int i2 = 0; i2 < 32; i2++) acc = fmaf(pp[i2], wrow[i2], acc);
#pragma unroll
        for (int o = 4; o > 0; o >>= 1) acc += __shfl_down_sync(0xffffffffu, acc, o, 8);
        if (part == 0) h_s[j] = fmaxf(acc + fc1_b[j], 0.f);
    }
    __syncthreads();

    const int c = threadIdx.x;
    const float* wa0 = fc2_w + (size_t)(2 * c) * HID;
    const float* wb0 = wa0 + HID;
    const float* wa1 = fc2_w + (size_t)(2 * CC + 2 * c) * HID;
    const float* wb1 = wa1 + HID;
    float da0 = fc2_b[2 * c];
    float db0 = fc2_b[2 * c + 1];
    float da1 = fc2_b[2 * CC + 2 * c];
    float db1 = fc2_b[2 * CC + 2 * c + 1];
#pragma unroll
    for (int j = 0; j < HID; j++) {
        float hj = h_s[j];
        da0 = fmaf(wa0[j], hj, da0);
        db0 = fmaf(wb0[j], hj, db0);
        da1 = fmaf(wa1[j], hj, da1);
        db1 = fmaf(wb1[j], hj, db1);
    }
    const int plane = b * CC + c;
    g_a0[plane] = 1.0f + tanhf(0.5f * da0);          // LAMBDA_ALPHA = 1.0
    g_c0[plane] = 1.0f + 0.5f * tanhf(0.5f * db0);   // LAMBDA_BETA  = 0.5
    g_a1[plane] = tanhf(0.5f * da1);
    g_c1[plane] = 0.5f * tanhf(0.5f * db1);
}

// ---------------------------------------------------------------------------
// Kernel 3: pure-TMA swarm apply (R15 winner, unchanged).
// ---------------------------------------------------------------------------
__global__ __launch_bounds__(64) void apply_tma64_kernel(const float* __restrict__ x,
                                                         float* __restrict__ out) {
    __shared__ alignas(16) float tile[HWL];
    __shared__ alignas(8) unsigned long long mbar;

    const int plane = (NPLANE - 1) - blockIdx.x;   // reverse traversal
    const int tid = threadIdx.x;
    const uint32_t mb = smem_u32(&mbar);
    const uint32_t ta = smem_u32(tile);

    if (tid == 0) {
        asm volatile("mbarrier.init.shared.b64 [%0], 1;" :: "r"(mb) : "memory");
        asm volatile("mbarrier.arrive.expect_tx.shared.b64 _, [%0], %1;"
                     :: "r"(mb), "r"((uint32_t)PLANE_BYTES) : "memory");
        asm volatile(
            "cp.async.bulk.shared::cluster.global.mbarrier::complete_tx::bytes "
            "[%0], [%1], %2, [%3];"
            :: "r"(ta), "l"(x + (size_t)plane * HWL),
               "r"((uint32_t)PLANE_BYTES), "r"(mb) : "memory");
    }
    __syncthreads();

    const float a0 = g_a0[plane];
    const float c0 = g_c0[plane];
    const float a1 = g_a1[plane];
    const float c1 = g_c1[plane];

    asm volatile(
        "{\n\t"
        ".reg .pred P;\n\t"
        "W_%=:\n\t"
        "mbarrier.try_wait.parity.shared.b64 P, [%0], 0;\n\t"
        "@!P bra W_%=;\n\t"
        "}"
        :: "r"(mb) : "memory");

    float4* t4 = reinterpret_cast<float4*>(tile);
#pragma unroll
    for (int k = 0; k < 12; k++) {
        float4 v = t4[tid + 64 * k];
        float4 r;
        r.x = fmaxf(fmaf(v.x, a0, c0), fmaf(v.x, a1, c1));
        r.y = fmaxf(fmaf(v.y, a0, c0), fmaf(v.y, a1, c1));
        r.z = fmaxf(fmaf(v.z, a0, c0), fmaf(v.z, a1, c1));
        r.w = fmaxf(fmaf(v.w, a0, c0), fmaf(v.w, a1, c1));
        t4[tid + 64 * k] = r;
    }
    if (tid < 16) {
        float4 v = t4[768 + tid];
        float4 r;
        r.x = fmaxf(fmaf(v.x, a0, c0), fmaf(v.x, a1, c1));
        r.y = fmaxf(fmaf(v.y, a0, c0), fmaf(v.y, a1, c1));
        r.z = fmaxf(fmaf(v.z, a0, c0), fmaf(v.z, a1, c1));
        r.w = fmaxf(fmaf(v.w, a0, c0), fmaf(v.w, a1, c1));
        t4[768 + tid] = r;
    }
    __syncthreads();

    if (tid == 0) {
        asm volatile("fence.proxy.async.shared::cta;" ::: "memory");
        asm volatile(
            "{\n\t"
            ".reg .b64 pol;\n\t"
            "createpolicy.fractional.L2::evict_first.b64 pol, 1.0;\n\t"
            "cp.async.bulk.global.shared::cta.bulk_group.L2::cache_hint "
            "[%0], [%1], %2, pol;\n\t"
            "}"
            :: "l"(out + (size_t)plane * HWL), "r"(ta),
               "r"((uint32_t)PLANE_BYTES) : "memory");
        asm volatile("cp.async.bulk.commit_group;" ::: "memory");
        asm volatile("cp.async.bulk.wait_group 0;" ::: "memory");
    }
}

extern "C" void kernel_launch(void* const* d_in, const int* in_sizes, int n_in,
                              void* d_out, int out_size) {
    const float* x      = (const float*)d_in[0];
    const float* fc1_w  = (const float*)d_in[1];
    const float* fc1_b  = (const float*)d_in[2];
    const float* fc2_w  = (const float*)d_in[3];
    const float* fc2_b  = (const float*)d_in[4];
    float* out = (float*)d_out;

    static bool configured = false;
    if (!configured) {
        cudaFuncSetAttribute(pool_tma64_kernel,
                             cudaFuncAttributePreferredSharedMemoryCarveout, 100);
        cudaFuncSetAttribute(apply_tma64_kernel,
                             cudaFuncAttributePreferredSharedMemoryCarveout, 100);
        configured = true;
    }

    pool_tma64_kernel<<<NPLANE, 64>>>(x);
    coef_kernel<<<BB, 256>>>(fc1_w, fc1_b, fc2_w, fc2_b);
    apply_tma64_kernel<<<NPLANE, 64>>>(x, out);
}